// round 13
// baseline (speedup 1.0000x reference)
#include <cuda_runtime.h>
#include <cuda_fp16.h>
#include <cstdint>
#include <math.h>

#define B_   16
#define C_   256
#define CIN  256
#define H_   128
#define W_   128
#define HW   (H_*W_)
#define TOT  ((size_t)B_*C_*HW)

// ---------------- device scratch (allocation-guard safe) -------------------
__device__ __half g_q[TOT];                       // fp16
__device__ __half g_k[TOT];
__device__ __half g_v[TOT];
__device__ __half g_x16[(size_t)B_*H_*W_*CIN];    // x transposed: [b][h][w][ci]
__device__ __half g_w16[(size_t)3*9*256*256];     // [t][kk][co][ci]

// ---------------- helpers ---------------------------------------------------
__device__ __forceinline__ uint32_t smem_u32(const void* p) {
    uint32_t a;
    asm("{ .reg .u64 t; cvta.to.shared.u64 t, %1; cvt.u32.u64 %0, t; }" : "=r"(a) : "l"(p));
    return a;
}
__device__ __forceinline__ void cpa16(uint32_t d, const void* s) {
    asm volatile("cp.async.cg.shared.global [%0], [%1], 16;" :: "r"(d), "l"(s));
}
__device__ __forceinline__ void cpa16z(uint32_t d, const void* s, int sz) {
    asm volatile("cp.async.cg.shared.global [%0], [%1], 16, %2;" :: "r"(d), "l"(s), "r"(sz));
}
#define CP_COMMIT() asm volatile("cp.async.commit_group;" ::: "memory")
#define CP_WAIT1()  asm volatile("cp.async.wait_group 1;" ::: "memory")
#define CP_WAIT0()  asm volatile("cp.async.wait_group 0;" ::: "memory")

__device__ __forceinline__ void mma16(float* c, const uint32_t* a, const uint32_t* b) {
    asm volatile(
        "mma.sync.aligned.m16n8k16.row.col.f32.f16.f16.f32 "
        "{%0,%1,%2,%3}, {%4,%5,%6,%7}, {%8,%9}, {%0,%1,%2,%3};"
        : "+f"(c[0]), "+f"(c[1]), "+f"(c[2]), "+f"(c[3])
        : "r"(a[0]), "r"(a[1]), "r"(a[2]), "r"(a[3]), "r"(b[0]), "r"(b[1]));
}

// ---------------- prologue 1: x NCHW f32 -> [b][h][w][ci] fp16 --------------
__global__ __launch_bounds__(256) void xcvt_kernel(const float* __restrict__ x) {
    __shared__ float t[32][33];
    const int bb = blockIdx.z;
    const int ci0 = blockIdx.y * 32, hw0 = blockIdx.x * 32;
    const int tx = threadIdx.x, ty = threadIdx.y;
    #pragma unroll
    for (int j = 0; j < 4; ++j)
        t[ty + 8 * j][tx] = x[(((size_t)bb * CIN + ci0 + ty + 8 * j) << 14) + hw0 + tx];
    __syncthreads();
    #pragma unroll
    for (int j = 0; j < 4; ++j)
        g_x16[(((size_t)bb << 14) + hw0 + ty + 8 * j) * CIN + ci0 + tx] =
            __float2half_rn(t[tx][ty + 8 * j]);
}

// ---------------- prologue 2: W [co][ci][3][3] -> [t][kk][co][ci] fp16 ------
__global__ __launch_bounds__(256) void wcvt_kernel(
    const float* __restrict__ Wq, const float* __restrict__ Wk, const float* __restrict__ Wv) {
    __shared__ float s[2304];
    const int co = blockIdx.x, t = blockIdx.y;
    const float* src = ((t == 0) ? Wq : (t == 1) ? Wk : Wv) + (size_t)co * 2304;
    for (int i = threadIdx.x; i < 2304; i += 256) s[i] = src[i];
    __syncthreads();
    const int ci = threadIdx.x;
    #pragma unroll
    for (int kk = 0; kk < 9; ++kk)
        g_w16[(((size_t)t * 9 + kk) * 256 + co) * 256 + ci] = __float2half_rn(s[ci * 9 + kk]);
}

// ---------------- conv: fp16 implicit GEMM, chunk=(kh,ci8), 2-stage ---------
// CTA: M=128 co x N=128 px, 256 thr / 8 warps, warp tile 32x64.
// Per chunk: 3 A tiles (one per kw) + 1 halo B tile; all 3 kw in one compute.
#define CSA      20                      // words per tile row (32 fp16 + pad)
#define A_TILE   (128 * CSA)             // 2560 words
#define A_ST     (3 * A_TILE)            // 7680 words per stage
#define B_ST     (130 * CSA)             // 2600 words per stage
#define SBB      (2 * A_ST)              // 15360
#define CONV_SMEM ((2 * A_ST + 2 * B_ST) * 4)   // 82240 B

__global__ __launch_bounds__(256, 2) void conv_kernel(
    const float* __restrict__ bq, const float* __restrict__ bk, const float* __restrict__ bv) {
    extern __shared__ uint32_t sm[];
    const int tid = threadIdx.x, lane = tid & 31, warp = tid >> 5;
    const int gid = lane >> 2, tig = lane & 3;
    const int cob = (warp >> 1) * 32, nb = (warp & 1) * 64;
    const int bh = blockIdx.x, t = blockIdx.y, cog = blockIdx.z;
    const int b = bh >> 7, h = bh & 127;
    const int kh0 = (h == 0) ? 1 : 0;
    const int kh1 = (h == 127) ? 1 : 2;
    const int nch = (kh1 - kh0 + 1) * 8;    // chunks: (kh)(ci8)
    const uint32_t smbase = smem_u32(sm);

    float acc[2][8][4];
    #pragma unroll
    for (int i = 0; i < 2; ++i)
        #pragma unroll
        for (int j = 0; j < 8; ++j)
            #pragma unroll
            for (int l = 0; l < 4; ++l) acc[i][j][l] = 0.f;

    auto fill = [&](int c) {
        const int kh = kh0 + (c >> 3);
        const int ci8 = c & 7;
        const int st = c & 1;
        // A: 3 kw tiles, 128 rows x 4 segs each (512 items -> i < 2)
        #pragma unroll
        for (int kw = 0; kw < 3; ++kw) {
            const __half* wp = g_w16 + (((size_t)t * 9 + kh * 3 + kw) * 256 + cog * 128) * 256
                             + ci8 * 32;
            const uint32_t dA = smbase + (st * A_ST + kw * A_TILE) * 4;
            #pragma unroll
            for (int i = 0; i < 2; ++i) {
                const int idx = tid + i * 256;
                const int row = idx >> 2, seg = idx & 3;
                cpa16(dA + (uint32_t)(row * CSA + seg * 4) * 4, wp + (size_t)row * 256 + seg * 8);
            }
        }
        // B: halo rows wsrc = -1..128 (row r -> wsrc r-1): 130 rows x 4 segs = 520
        const int hsrc = h + kh - 1;
        const __half* xp = g_x16 + (((size_t)(b * H_ + hsrc)) << 7) * 256 + ci8 * 32;
        const uint32_t dB = smbase + (SBB + st * B_ST) * 4;
        #pragma unroll
        for (int i = 0; i < 3; ++i) {
            const int idx = tid + i * 256;
            if (idx < 520) {
                const int row = idx >> 2, seg = idx & 3;
                const int wsrc = row - 1;
                const int sz = ((unsigned)wsrc < 128u) ? 16 : 0;
                const int wc = min(max(wsrc, 0), 127);
                cpa16z(dB + (uint32_t)(row * CSA + seg * 4) * 4,
                       xp + (size_t)wc * 256 + seg * 8, sz);
            }
        }
    };

    auto compute = [&](int c) {
        const int st = c & 1;
        #pragma unroll
        for (int kw = 0; kw < 3; ++kw) {
            const uint32_t* A  = sm + st * A_ST + kw * A_TILE;
            const uint32_t* Bp = sm + SBB + st * B_ST + kw * CSA;
            #pragma unroll
            for (int ks = 0; ks < 2; ++ks) {
                const int k0 = ks * 8;   // word offset (16 fp16)
                uint32_t af[2][4], bf[8][2];
                #pragma unroll
                for (int mi = 0; mi < 2; ++mi) {
                    const int r = (cob + mi * 16 + gid) * CSA + k0 + tig;
                    af[mi][0] = A[r];
                    af[mi][1] = A[r + 8 * CSA];
                    af[mi][2] = A[r + 4];
                    af[mi][3] = A[r + 8 * CSA + 4];
                }
                #pragma unroll
                for (int ni = 0; ni < 8; ++ni) {
                    const int r = (nb + ni * 8 + gid) * CSA + k0 + tig;
                    bf[ni][0] = Bp[r];
                    bf[ni][1] = Bp[r + 4];
                }
                #pragma unroll
                for (int mi = 0; mi < 2; ++mi)
                    #pragma unroll
                    for (int ni = 0; ni < 8; ++ni)
                        mma16(acc[mi][ni], af[mi], bf[ni]);
            }
        }
    };

    fill(0); CP_COMMIT();
    for (int it = 0; it < nch; ++it) {
        if (it + 1 < nch) { fill(it + 1); CP_COMMIT(); CP_WAIT1(); }
        else              { CP_WAIT0(); }
        __syncthreads();
        compute(it);
        __syncthreads();
    }

    // epilogue: bias + store fp16
    __half* outp = (t == 0) ? g_q : (t == 1) ? g_k : g_v;
    const float* bias = (t == 0) ? bq : (t == 1) ? bk : bv;
    #pragma unroll
    for (int mi = 0; mi < 2; ++mi) {
        const int co0 = cog * 128 + cob + mi * 16 + gid;
        const float bv0 = bias[co0], bv1 = bias[co0 + 8];
        __half* r0 = outp + ((size_t)(b * C_ + co0) * HW) + h * 128;
        __half* r1 = r0 + (size_t)8 * HW;
        #pragma unroll
        for (int ni = 0; ni < 8; ++ni) {
            const int col = nb + ni * 8 + 2 * tig;
            *(__half2*)(r0 + col) = __floats2half2_rn(acc[mi][ni][0] + bv0, acc[mi][ni][1] + bv0);
            *(__half2*)(r1 + col) = __floats2half2_rn(acc[mi][ni][2] + bv1, acc[mi][ni][3] + bv1);
        }
    }
}

// ---------------- attention: fp16 tensor-core, 2 CTAs/SM --------------------
// Regions: Q (reused for P), K (reused for V^T), V. 3 regions -> 102 KB.
#define ASW 68                                  // words per row (128 fp16 + 8 pad)
#define AREG (128 * ASW)
#define ATTN_SMEM (3 * AREG * 4)                // 104448 B

__global__ __launch_bounds__(256, 2) void attn_kernel(float* __restrict__ out) {
    extern __shared__ uint32_t asm_[];
    uint32_t* qs  = asm_;
    uint32_t* ks  = qs + AREG;
    uint32_t* vs  = ks + AREG;
    uint32_t* vts = ks;                         // V^T overwrites K after S-GEMM

    const int bc = blockIdx.x;
    const size_t base = (size_t)bc * HW;
    const int tid = threadIdx.x;
    const int lane = tid & 31;
    const int warp = tid >> 5;
    const int gid = lane >> 2, tig = lane & 3;
    const uint32_t smbase = smem_u32(asm_);

    // group 0: Q + K
    #pragma unroll
    for (int i = 0; i < 8; ++i) {
        const int idx = tid + i * 256;
        const int r = idx >> 4, seg = idx & 15;
        const uint32_t doff = (uint32_t)(r * ASW + seg * 4) * 4;
        cpa16(smbase + doff,            g_q + base + (size_t)r * 128 + seg * 8);
        cpa16(smbase + AREG * 4 + doff, g_k + base + (size_t)r * 128 + seg * 8);
    }
    CP_COMMIT();
    // group 1: V (overlaps S + softmax)
    #pragma unroll
    for (int i = 0; i < 8; ++i) {
        const int idx = tid + i * 256;
        const int r = idx >> 4, seg = idx & 15;
        cpa16(smbase + 2 * AREG * 4 + (uint32_t)(r * ASW + seg * 4) * 4,
              g_v + base + (size_t)r * 128 + seg * 8);
    }
    CP_COMMIT();
    CP_WAIT1();
    __syncthreads();

    const uint32_t* qw = qs + warp * 16 * ASW;
    uint32_t* pw = qs + warp * 16 * ASW;

    // ---- S = Q K^T ----
    float sacc[16][4];
    #pragma unroll
    for (int nt = 0; nt < 16; ++nt)
        #pragma unroll
        for (int j = 0; j < 4; ++j) sacc[nt][j] = 0.f;

    #pragma unroll
    for (int kt = 0; kt < 8; ++kt) {
        const int k0 = kt * 8;
        uint32_t a[4];
        a[0] = qw[gid * ASW + k0 + tig];
        a[1] = qw[(gid + 8) * ASW + k0 + tig];
        a[2] = qw[gid * ASW + k0 + tig + 4];
        a[3] = qw[(gid + 8) * ASW + k0 + tig + 4];
        #pragma unroll
        for (int nt = 0; nt < 16; ++nt) {
            uint32_t b[2];
            b[0] = ks[(nt * 8 + gid) * ASW + k0 + tig];
            b[1] = ks[(nt * 8 + gid) * ASW + k0 + tig + 4];
            mma16(sacc[nt], a, b);
        }
    }

    // ---- softmax ----
    const float scale = rsqrtf(128.f);
    float m0 = -1e30f, m1 = -1e30f;
    #pragma unroll
    for (int nt = 0; nt < 16; ++nt) {
        #pragma unroll
        for (int j = 0; j < 4; ++j) sacc[nt][j] *= scale;
        m0 = fmaxf(m0, fmaxf(sacc[nt][0], sacc[nt][1]));
        m1 = fmaxf(m1, fmaxf(sacc[nt][2], sacc[nt][3]));
    }
    m0 = fmaxf(m0, __shfl_xor_sync(0xffffffffu, m0, 1));
    m0 = fmaxf(m0, __shfl_xor_sync(0xffffffffu, m0, 2));
    m1 = fmaxf(m1, __shfl_xor_sync(0xffffffffu, m1, 1));
    m1 = fmaxf(m1, __shfl_xor_sync(0xffffffffu, m1, 2));

    float e0 = 0.f, e1 = 0.f;
    #pragma unroll
    for (int nt = 0; nt < 16; ++nt) {
        sacc[nt][0] = __expf(sacc[nt][0] - m0);
        sacc[nt][1] = __expf(sacc[nt][1] - m0);
        sacc[nt][2] = __expf(sacc[nt][2] - m1);
        sacc[nt][3] = __expf(sacc[nt][3] - m1);
        e0 += sacc[nt][0] + sacc[nt][1];
        e1 += sacc[nt][2] + sacc[nt][3];
    }
    e0 += __shfl_xor_sync(0xffffffffu, e0, 1);
    e0 += __shfl_xor_sync(0xffffffffu, e0, 2);
    e1 += __shfl_xor_sync(0xffffffffu, e1, 1);
    e1 += __shfl_xor_sync(0xffffffffu, e1, 2);
    const float i0 = 1.f / e0, i1 = 1.f / e1;

    // store P (fp16 pairs) into warp's own Q region
    #pragma unroll
    for (int nt = 0; nt < 16; ++nt) {
        __half2 p0 = __floats2half2_rn(sacc[nt][0] * i0, sacc[nt][1] * i0);
        __half2 p1 = __floats2half2_rn(sacc[nt][2] * i1, sacc[nt][3] * i1);
        pw[gid * ASW + nt * 4 + tig]       = *(uint32_t*)&p0;
        pw[(gid + 8) * ASW + nt * 4 + tig] = *(uint32_t*)&p1;
    }
    __syncwarp();

    CP_WAIT0();
    __syncthreads();   // all warps done reading K; V landed

    // ---- transpose V: vs[g][w] -> vts[w][g] (vts overlays ks) ----
    {
        uint16_t* vth = (uint16_t*)vts;
        const int g = tid >> 1;
        const int wb = (tid & 1) * 64;
        #pragma unroll
        for (int w2 = 0; w2 < 32; ++w2) {
            const int w = wb + w2 * 2;
            const uint32_t pair = vs[g * ASW + (w >> 1)];
            vth[(size_t)w * (2 * ASW) + g]       = (uint16_t)(pair & 0xffff);
            vth[(size_t)(w + 1) * (2 * ASW) + g] = (uint16_t)(pair >> 16);
        }
    }
    __syncthreads();

    // ---- O = P V ----
    float oacc[16][4];
    #pragma unroll
    for (int nt = 0; nt < 16; ++nt)
        #pragma unroll
        for (int j = 0; j < 4; ++j) oacc[nt][j] = 0.f;

    #pragma unroll
    for (int kt = 0; kt < 8; ++kt) {
        const int k0 = kt * 8;
        uint32_t a[4];
        a[0] = pw[gid * ASW + k0 + tig];
        a[1] = pw[(gid + 8) * ASW + k0 + tig];
        a[2] = pw[gid * ASW + k0 + tig + 4];
        a[3] = pw[(gid + 8) * ASW + k0 + tig + 4];
        #pragma unroll
        for (int nt = 0; nt < 16; ++nt) {
            uint32_t b[2];
            b[0] = vts[(nt * 8 + gid) * ASW + k0 + tig];
            b[1] = vts[(nt * 8 + gid) * ASW + k0 + tig + 4];
            mma16(oacc[nt], a, b);
        }
    }

    float* op0 = out + base + (size_t)(warp * 16 + gid) * 128;
    float* op1 = op0 + 8 * 128;
    #pragma unroll
    for (int nt = 0; nt < 16; ++nt) {
        const int col = nt * 8 + 2 * tig;
        *(float2*)(op0 + col) = make_float2(oacc[nt][0], oacc[nt][1]);
        *(float2*)(op1 + col) = make_float2(oacc[nt][2], oacc[nt][3]);
    }
}

// ---------------------------------------------------------------------------
extern "C" void kernel_launch(void* const* d_in, const int* in_sizes, int n_in,
                              void* d_out, int out_size) {
    const float* x  = (const float*)d_in[0];
    const float* Wq = (const float*)d_in[1];
    const float* bq = (const float*)d_in[2];
    const float* Wk = (const float*)d_in[3];
    const float* bk = (const float*)d_in[4];
    const float* Wv = (const float*)d_in[5];
    const float* bv = (const float*)d_in[6];
    float* out = (float*)d_out;

    static bool attr_done = false;
    if (!attr_done) {
        cudaFuncSetAttribute(conv_kernel, cudaFuncAttributeMaxDynamicSharedMemorySize, CONV_SMEM);
        cudaFuncSetAttribute(attn_kernel, cudaFuncAttributeMaxDynamicSharedMemorySize, ATTN_SMEM);
        attr_done = true;
    }

    xcvt_kernel<<<dim3(512, 8, 16), dim3(32, 8)>>>(x);
    wcvt_kernel<<<dim3(256, 3), 256>>>(Wq, Wk, Wv);

    conv_kernel<<<dim3(B_ * H_, 3, 2), 256, CONV_SMEM>>>(bq, bk, bv);

    attn_kernel<<<B_ * C_, 256, ATTN_SMEM>>>(out);
}

// round 14
// speedup vs baseline: 1.0453x; 1.0453x over previous
#include <cuda_runtime.h>
#include <cuda_fp16.h>
#include <cstdint>
#include <math.h>

#define B_   16
#define C_   256
#define CIN  256
#define H_   128
#define W_   128
#define HW   (H_*W_)
#define TOT  ((size_t)B_*C_*HW)

// ---------------- device scratch (allocation-guard safe) -------------------
__device__ __half g_q[TOT];                       // fp16
__device__ __half g_k[TOT];
__device__ __half g_v[TOT];
__device__ __half g_x16[(size_t)B_*H_*W_*CIN];    // x transposed: [b][h][w][ci]
__device__ __half g_w16[(size_t)3*9*256*256];     // [t][kk][co][ci]

// ---------------- helpers ---------------------------------------------------
__device__ __forceinline__ uint32_t smem_u32(const void* p) {
    uint32_t a;
    asm("{ .reg .u64 t; cvta.to.shared.u64 t, %1; cvt.u32.u64 %0, t; }" : "=r"(a) : "l"(p));
    return a;
}
__device__ __forceinline__ void cpa16(uint32_t d, const void* s) {
    asm volatile("cp.async.cg.shared.global [%0], [%1], 16;" :: "r"(d), "l"(s));
}
__device__ __forceinline__ void cpa16z(uint32_t d, const void* s, int sz) {
    asm volatile("cp.async.cg.shared.global [%0], [%1], 16, %2;" :: "r"(d), "l"(s), "r"(sz));
}
#define CP_COMMIT() asm volatile("cp.async.commit_group;" ::: "memory")
#define CP_WAIT1()  asm volatile("cp.async.wait_group 1;" ::: "memory")
#define CP_WAIT0()  asm volatile("cp.async.wait_group 0;" ::: "memory")

__device__ __forceinline__ void mma16(float* c, const uint32_t* a, const uint32_t* b) {
    asm volatile(
        "mma.sync.aligned.m16n8k16.row.col.f32.f16.f16.f32 "
        "{%0,%1,%2,%3}, {%4,%5,%6,%7}, {%8,%9}, {%0,%1,%2,%3};"
        : "+f"(c[0]), "+f"(c[1]), "+f"(c[2]), "+f"(c[3])
        : "r"(a[0]), "r"(a[1]), "r"(a[2]), "r"(a[3]), "r"(b[0]), "r"(b[1]));
}

// ---------------- prologue 1: x NCHW f32 -> [b][h][w][ci] fp16 --------------
__global__ __launch_bounds__(256) void xcvt_kernel(const float* __restrict__ x) {
    __shared__ float t[32][33];
    const int bb = blockIdx.z;
    const int ci0 = blockIdx.y * 32, hw0 = blockIdx.x * 32;
    const int tx = threadIdx.x, ty = threadIdx.y;
    #pragma unroll
    for (int j = 0; j < 4; ++j)
        t[ty + 8 * j][tx] = x[(((size_t)bb * CIN + ci0 + ty + 8 * j) << 14) + hw0 + tx];
    __syncthreads();
    #pragma unroll
    for (int j = 0; j < 4; ++j)
        g_x16[(((size_t)bb << 14) + hw0 + ty + 8 * j) * CIN + ci0 + tx] =
            __float2half_rn(t[tx][ty + 8 * j]);
}

// ---------------- prologue 2: W [co][ci][3][3] -> [t][kk][co][ci] fp16 ------
__global__ __launch_bounds__(256) void wcvt_kernel(
    const float* __restrict__ Wq, const float* __restrict__ Wk, const float* __restrict__ Wv) {
    __shared__ float s[2304];
    const int co = blockIdx.x, t = blockIdx.y;
    const float* src = ((t == 0) ? Wq : (t == 1) ? Wk : Wv) + (size_t)co * 2304;
    for (int i = threadIdx.x; i < 2304; i += 256) s[i] = src[i];
    __syncthreads();
    const int ci = threadIdx.x;
    #pragma unroll
    for (int kk = 0; kk < 9; ++kk)
        g_w16[(((size_t)t * 9 + kk) * 256 + co) * 256 + ci] = __float2half_rn(s[ci * 9 + kk]);
}

// ---------------- conv: fp16 implicit GEMM, kw-chunks, 3-stage, 2 CTAs/SM ---
// CTA: M=128 co x N=128 px, 256 thr / 8 warps, warp tile 32x64.
// A [co][ci32] fp16 (stride 20 words), B halo [130 px-rows][ci32] (stride 20).
#define CSA      20                      // words per A row (32 fp16 + pad)
#define A_WORDS  (128 * CSA)             // 2560
#define B_WORDS  (130 * CSA)             // 2600
#define SBB      (3 * A_WORDS)
#define CONV_SMEM ((3 * A_WORDS + 3 * B_WORDS) * 4)   // 61920 B

__global__ __launch_bounds__(256, 2) void conv_kernel(
    const float* __restrict__ bq, const float* __restrict__ bk, const float* __restrict__ bv) {
    extern __shared__ uint32_t sm[];
    const int tid = threadIdx.x, lane = tid & 31, warp = tid >> 5;
    const int gid = lane >> 2, tig = lane & 3;
    const int cob = (warp >> 1) * 32, nb = (warp & 1) * 64;
    const int bh = blockIdx.x, t = blockIdx.y, cog = blockIdx.z;
    const int b = bh >> 7, h = bh & 127;
    const int kh0 = (h == 0) ? 1 : 0;
    const int kh1 = (h == 127) ? 1 : 2;
    const int nch = (kh1 - kh0 + 1) * 24;   // chunks: (kh)(ci8)(kw), kw fastest
    const uint32_t smbase = smem_u32(sm);

    float acc[2][8][4];
    #pragma unroll
    for (int i = 0; i < 2; ++i)
        #pragma unroll
        for (int j = 0; j < 8; ++j)
            #pragma unroll
            for (int l = 0; l < 4; ++l) acc[i][j][l] = 0.f;

    auto fill = [&](int it) {
        const int kh = kh0 + it / 24;
        const int rem = it % 24;
        const int ci8 = rem / 3, kw = rem % 3;
        // A: [t][kh*3+kw][cog*128 + row][ci8*32 + ...]
        const __half* wp = g_w16 + (((size_t)t * 9 + kh * 3 + kw) * 256 + cog * 128) * 256
                         + ci8 * 32;
        const uint32_t dA = smbase + ((it % 3) * A_WORDS) * 4;
        #pragma unroll
        for (int i = 0; i < 2; ++i) {
            const int idx = tid + i * 256;
            const int row = idx >> 2, seg = idx & 3;
            cpa16(dA + (uint32_t)(row * CSA + seg * 4) * 4, wp + (size_t)row * 256 + seg * 8);
        }
        // B: halo rows w-1..128 — only when kw == 0
        if (kw == 0) {
            const int hsrc = h + kh - 1;
            const __half* xp = g_x16 + (((size_t)(b * H_ + hsrc)) << 7) * 256 + ci8 * 32;
            const uint32_t dB = smbase + (SBB + ((it / 3) % 3) * B_WORDS) * 4;
            #pragma unroll
            for (int i = 0; i < 3; ++i) {
                const int idx = tid + i * 256;
                if (idx < 520) {
                    const int row = idx >> 2, seg = idx & 3;
                    const int wsrc = row - 1;
                    const int sz = ((unsigned)wsrc < 128u) ? 16 : 0;
                    const int wc = min(max(wsrc, 0), 127);
                    cpa16z(dB + (uint32_t)(row * CSA + seg * 4) * 4,
                           xp + (size_t)wc * 256 + seg * 8, sz);
                }
            }
        }
    };

    auto compute = [&](int it) {
        const int kw = it % 3;
        const uint32_t* A  = sm + (it % 3) * A_WORDS;
        const uint32_t* Bp = sm + SBB + ((it / 3) % 3) * B_WORDS + kw * CSA;
        #pragma unroll
        for (int ks = 0; ks < 2; ++ks) {
            const int k0 = ks * 8;   // word offset (16 fp16)
            uint32_t af[2][4], bf[8][2];
            #pragma unroll
            for (int mi = 0; mi < 2; ++mi) {
                const int r = (cob + mi * 16 + gid) * CSA + k0 + tig;
                af[mi][0] = A[r];
                af[mi][1] = A[r + 8 * CSA];
                af[mi][2] = A[r + 4];
                af[mi][3] = A[r + 8 * CSA + 4];
            }
            #pragma unroll
            for (int ni = 0; ni < 8; ++ni) {
                const int r = (nb + ni * 8 + gid) * CSA + k0 + tig;
                bf[ni][0] = Bp[r];
                bf[ni][1] = Bp[r + 4];
            }
            #pragma unroll
            for (int mi = 0; mi < 2; ++mi)
                #pragma unroll
                for (int ni = 0; ni < 8; ++ni)
                    mma16(acc[mi][ni], af[mi], bf[ni]);
        }
    };

    fill(0); CP_COMMIT();
    fill(1); CP_COMMIT();
    for (int it = 0; it < nch; ++it) {
        CP_WAIT1();
        __syncthreads();
        if (it + 2 < nch) fill(it + 2);
        CP_COMMIT();
        compute(it);
    }

    // epilogue: bias + store fp16
    __half* outp = (t == 0) ? g_q : (t == 1) ? g_k : g_v;
    const float* bias = (t == 0) ? bq : (t == 1) ? bk : bv;
    #pragma unroll
    for (int mi = 0; mi < 2; ++mi) {
        const int co0 = cog * 128 + cob + mi * 16 + gid;
        const float bv0 = bias[co0], bv1 = bias[co0 + 8];
        __half* r0 = outp + ((size_t)(b * C_ + co0) * HW) + h * 128;
        __half* r1 = r0 + (size_t)8 * HW;
        #pragma unroll
        for (int ni = 0; ni < 8; ++ni) {
            const int col = nb + ni * 8 + 2 * tig;
            *(__half2*)(r0 + col) = __floats2half2_rn(acc[mi][ni][0] + bv0, acc[mi][ni][1] + bv0);
            *(__half2*)(r1 + col) = __floats2half2_rn(acc[mi][ni][2] + bv1, acc[mi][ni][3] + bv1);
        }
    }
}

// ---------------- attention: fp16 tensor-core, 2 CTAs/SM --------------------
// Regions: Q (reused for P), K (reused for V^T), V. 3 regions -> 102 KB.
#define ASW 68                                  // words per row (128 fp16 + 8 pad)
#define AREG (128 * ASW)
#define ATTN_SMEM (3 * AREG * 4)                // 104448 B

__global__ __launch_bounds__(256, 2) void attn_kernel(float* __restrict__ out) {
    extern __shared__ uint32_t asm_[];
    uint32_t* qs  = asm_;
    uint32_t* ks  = qs + AREG;
    uint32_t* vs  = ks + AREG;
    uint32_t* vts = ks;                         // V^T overwrites K after S-GEMM

    const int bc = blockIdx.x;
    const size_t base = (size_t)bc * HW;
    const int tid = threadIdx.x;
    const int lane = tid & 31;
    const int warp = tid >> 5;
    const int gid = lane >> 2, tig = lane & 3;
    const uint32_t smbase = smem_u32(asm_);

    // group 0: Q + K
    #pragma unroll
    for (int i = 0; i < 8; ++i) {
        const int idx = tid + i * 256;
        const int r = idx >> 4, seg = idx & 15;
        const uint32_t doff = (uint32_t)(r * ASW + seg * 4) * 4;
        cpa16(smbase + doff,            g_q + base + (size_t)r * 128 + seg * 8);
        cpa16(smbase + AREG * 4 + doff, g_k + base + (size_t)r * 128 + seg * 8);
    }
    CP_COMMIT();
    // group 1: V (overlaps S + softmax)
    #pragma unroll
    for (int i = 0; i < 8; ++i) {
        const int idx = tid + i * 256;
        const int r = idx >> 4, seg = idx & 15;
        cpa16(smbase + 2 * AREG * 4 + (uint32_t)(r * ASW + seg * 4) * 4,
              g_v + base + (size_t)r * 128 + seg * 8);
    }
    CP_COMMIT();
    CP_WAIT1();
    __syncthreads();

    const uint32_t* qw = qs + warp * 16 * ASW;
    uint32_t* pw = qs + warp * 16 * ASW;

    // ---- S = Q K^T ----
    float sacc[16][4];
    #pragma unroll
    for (int nt = 0; nt < 16; ++nt)
        #pragma unroll
        for (int j = 0; j < 4; ++j) sacc[nt][j] = 0.f;

    #pragma unroll
    for (int kt = 0; kt < 8; ++kt) {
        const int k0 = kt * 8;
        uint32_t a[4];
        a[0] = qw[gid * ASW + k0 + tig];
        a[1] = qw[(gid + 8) * ASW + k0 + tig];
        a[2] = qw[gid * ASW + k0 + tig + 4];
        a[3] = qw[(gid + 8) * ASW + k0 + tig + 4];
        #pragma unroll
        for (int nt = 0; nt < 16; ++nt) {
            uint32_t b[2];
            b[0] = ks[(nt * 8 + gid) * ASW + k0 + tig];
            b[1] = ks[(nt * 8 + gid) * ASW + k0 + tig + 4];
            mma16(sacc[nt], a, b);
        }
    }

    // ---- softmax ----
    const float scale = rsqrtf(128.f);
    float m0 = -1e30f, m1 = -1e30f;
    #pragma unroll
    for (int nt = 0; nt < 16; ++nt) {
        #pragma unroll
        for (int j = 0; j < 4; ++j) sacc[nt][j] *= scale;
        m0 = fmaxf(m0, fmaxf(sacc[nt][0], sacc[nt][1]));
        m1 = fmaxf(m1, fmaxf(sacc[nt][2], sacc[nt][3]));
    }
    m0 = fmaxf(m0, __shfl_xor_sync(0xffffffffu, m0, 1));
    m0 = fmaxf(m0, __shfl_xor_sync(0xffffffffu, m0, 2));
    m1 = fmaxf(m1, __shfl_xor_sync(0xffffffffu, m1, 1));
    m1 = fmaxf(m1, __shfl_xor_sync(0xffffffffu, m1, 2));

    float e0 = 0.f, e1 = 0.f;
    #pragma unroll
    for (int nt = 0; nt < 16; ++nt) {
        sacc[nt][0] = __expf(sacc[nt][0] - m0);
        sacc[nt][1] = __expf(sacc[nt][1] - m0);
        sacc[nt][2] = __expf(sacc[nt][2] - m1);
        sacc[nt][3] = __expf(sacc[nt][3] - m1);
        e0 += sacc[nt][0] + sacc[nt][1];
        e1 += sacc[nt][2] + sacc[nt][3];
    }
    e0 += __shfl_xor_sync(0xffffffffu, e0, 1);
    e0 += __shfl_xor_sync(0xffffffffu, e0, 2);
    e1 += __shfl_xor_sync(0xffffffffu, e1, 1);
    e1 += __shfl_xor_sync(0xffffffffu, e1, 2);
    const float i0 = 1.f / e0, i1 = 1.f / e1;

    // store P (fp16 pairs) into warp's own Q region
    #pragma unroll
    for (int nt = 0; nt < 16; ++nt) {
        __half2 p0 = __floats2half2_rn(sacc[nt][0] * i0, sacc[nt][1] * i0);
        __half2 p1 = __floats2half2_rn(sacc[nt][2] * i1, sacc[nt][3] * i1);
        pw[gid * ASW + nt * 4 + tig]       = *(uint32_t*)&p0;
        pw[(gid + 8) * ASW + nt * 4 + tig] = *(uint32_t*)&p1;
    }
    __syncwarp();

    CP_WAIT0();
    __syncthreads();   // all warps done reading K; V landed

    // ---- transpose V: vs[g][w] -> vts[w][g] (vts overlays ks) ----
    {
        uint16_t* vth = (uint16_t*)vts;
        const int g = tid >> 1;
        const int wb = (tid & 1) * 64;
        #pragma unroll
        for (int w2 = 0; w2 < 32; ++w2) {
            const int w = wb + w2 * 2;
            const uint32_t pair = vs[g * ASW + (w >> 1)];
            vth[(size_t)w * (2 * ASW) + g]       = (uint16_t)(pair & 0xffff);
            vth[(size_t)(w + 1) * (2 * ASW) + g] = (uint16_t)(pair >> 16);
        }
    }
    __syncthreads();

    // ---- O = P V ----
    float oacc[16][4];
    #pragma unroll
    for (int nt = 0; nt < 16; ++nt)
        #pragma unroll
        for (int j = 0; j < 4; ++j) oacc[nt][j] = 0.f;

    #pragma unroll
    for (int kt = 0; kt < 8; ++kt) {
        const int k0 = kt * 8;
        uint32_t a[4];
        a[0] = pw[gid * ASW + k0 + tig];
        a[1] = pw[(gid + 8) * ASW + k0 + tig];
        a[2] = pw[gid * ASW + k0 + tig + 4];
        a[3] = pw[(gid + 8) * ASW + k0 + tig + 4];
        #pragma unroll
        for (int nt = 0; nt < 16; ++nt) {
            uint32_t b[2];
            b[0] = vts[(nt * 8 + gid) * ASW + k0 + tig];
            b[1] = vts[(nt * 8 + gid) * ASW + k0 + tig + 4];
            mma16(oacc[nt], a, b);
        }
    }

    float* op0 = out + base + (size_t)(warp * 16 + gid) * 128;
    float* op1 = op0 + 8 * 128;
    #pragma unroll
    for (int nt = 0; nt < 16; ++nt) {
        const int col = nt * 8 + 2 * tig;
        *(float2*)(op0 + col) = make_float2(oacc[nt][0], oacc[nt][1]);
        *(float2*)(op1 + col) = make_float2(oacc[nt][2], oacc[nt][3]);
    }
}

// ---------------------------------------------------------------------------
extern "C" void kernel_launch(void* const* d_in, const int* in_sizes, int n_in,
                              void* d_out, int out_size) {
    const float* x  = (const float*)d_in[0];
    const float* Wq = (const float*)d_in[1];
    const float* bq = (const float*)d_in[2];
    const float* Wk = (const float*)d_in[3];
    const float* bk = (const float*)d_in[4];
    const float* Wv = (const float*)d_in[5];
    const float* bv = (const float*)d_in[6];
    float* out = (float*)d_out;

    static bool attr_done = false;
    if (!attr_done) {
        cudaFuncSetAttribute(conv_kernel, cudaFuncAttributeMaxDynamicSharedMemorySize, CONV_SMEM);
        cudaFuncSetAttribute(attn_kernel, cudaFuncAttributeMaxDynamicSharedMemorySize, ATTN_SMEM);
        attr_done = true;
    }

    xcvt_kernel<<<dim3(512, 8, 16), dim3(32, 8)>>>(x);
    wcvt_kernel<<<dim3(256, 3), 256>>>(Wq, Wk, Wv);

    conv_kernel<<<dim3(B_ * H_, 3, 2), 256, CONV_SMEM>>>(bq, bk, bv);

    attn_kernel<<<B_ * C_, 256, ATTN_SMEM>>>(out);
}

// round 15
// speedup vs baseline: 1.0575x; 1.0117x over previous
#include <cuda_runtime.h>
#include <cuda_fp16.h>
#include <cstdint>
#include <math.h>

#define B_   16
#define C_   256
#define CIN  256
#define H_   128
#define W_   128
#define HW   (H_*W_)
#define TOT  ((size_t)B_*C_*HW)

// ---------------- device scratch (allocation-guard safe) -------------------
__device__ __half g_q[TOT];                       // fp16
__device__ __half g_k[TOT];
__device__ __half g_v[TOT];
__device__ __half g_x16[(size_t)B_*H_*W_*CIN];    // x transposed: [b][h][w][ci]
__device__ __half g_w16[(size_t)3*9*256*256];     // [t][kk][co][ci]

// ---------------- helpers ---------------------------------------------------
__device__ __forceinline__ uint32_t smem_u32(const void* p) {
    uint32_t a;
    asm("{ .reg .u64 t; cvta.to.shared.u64 t, %1; cvt.u32.u64 %0, t; }" : "=r"(a) : "l"(p));
    return a;
}
__device__ __forceinline__ void cpa16(uint32_t d, const void* s) {
    asm volatile("cp.async.cg.shared.global [%0], [%1], 16;" :: "r"(d), "l"(s));
}
__device__ __forceinline__ void cpa16z(uint32_t d, const void* s, int sz) {
    asm volatile("cp.async.cg.shared.global [%0], [%1], 16, %2;" :: "r"(d), "l"(s), "r"(sz));
}
#define CP_COMMIT() asm volatile("cp.async.commit_group;" ::: "memory")
#define CP_WAIT2()  asm volatile("cp.async.wait_group 2;" ::: "memory")
#define CP_WAIT1()  asm volatile("cp.async.wait_group 1;" ::: "memory")
#define CP_WAIT0()  asm volatile("cp.async.wait_group 0;" ::: "memory")

__device__ __forceinline__ void mma16(float* c, const uint32_t* a, const uint32_t* b) {
    asm volatile(
        "mma.sync.aligned.m16n8k16.row.col.f32.f16.f16.f32 "
        "{%0,%1,%2,%3}, {%4,%5,%6,%7}, {%8,%9}, {%0,%1,%2,%3};"
        : "+f"(c[0]), "+f"(c[1]), "+f"(c[2]), "+f"(c[3])
        : "r"(a[0]), "r"(a[1]), "r"(a[2]), "r"(a[3]), "r"(b[0]), "r"(b[1]));
}

// ---------------- prologue 1: x NCHW f32 -> [b][h][w][ci] fp16 --------------
__global__ __launch_bounds__(256) void xcvt_kernel(const float* __restrict__ x) {
    __shared__ float t[32][33];
    const int bb = blockIdx.z;
    const int ci0 = blockIdx.y * 32, hw0 = blockIdx.x * 32;
    const int tx = threadIdx.x, ty = threadIdx.y;
    #pragma unroll
    for (int j = 0; j < 4; ++j)
        t[ty + 8 * j][tx] = x[(((size_t)bb * CIN + ci0 + ty + 8 * j) << 14) + hw0 + tx];
    __syncthreads();
    #pragma unroll
    for (int j = 0; j < 4; ++j)
        g_x16[(((size_t)bb << 14) + hw0 + ty + 8 * j) * CIN + ci0 + tx] =
            __float2half_rn(t[tx][ty + 8 * j]);
}

// ---------------- prologue 2: W [co][ci][3][3] -> [t][kk][co][ci] fp16 ------
__global__ __launch_bounds__(256) void wcvt_kernel(
    const float* __restrict__ Wq, const float* __restrict__ Wk, const float* __restrict__ Wv) {
    __shared__ float s[2304];
    const int co = blockIdx.x, t = blockIdx.y;
    const float* src = ((t == 0) ? Wq : (t == 1) ? Wk : Wv) + (size_t)co * 2304;
    for (int i = threadIdx.x; i < 2304; i += 256) s[i] = src[i];
    __syncthreads();
    const int ci = threadIdx.x;
    #pragma unroll
    for (int kk = 0; kk < 9; ++kk)
        g_w16[(((size_t)t * 9 + kk) * 256 + co) * 256 + ci] = __float2half_rn(s[ci * 9 + kk]);
}

// ---------------- conv: fp16 implicit GEMM, 6-stage A ring, paired chunks ---
// CTA: M=128 co x N=128 px, 256 thr / 8 warps, warp tile 32x64.
// A [co][ci32] fp16 (stride 20 words) x 6 stages; B halo [130 rows][ci32] x 3.
// One barrier + one wait per 2 chunks; fills run 2-4 chunks ahead.
#define CSA      20                      // words per A row (32 fp16 + pad)
#define A_WORDS  (128 * CSA)             // 2560
#define B_WORDS  (130 * CSA)             // 2600
#define NSTG     6
#define SBB      (NSTG * A_WORDS)        // 15360
#define CONV_SMEM ((NSTG * A_WORDS + 3 * B_WORDS) * 4)   // 92640 B

__global__ __launch_bounds__(256, 2) void conv_kernel(
    const float* __restrict__ bq, const float* __restrict__ bk, const float* __restrict__ bv) {
    extern __shared__ uint32_t sm[];
    const int tid = threadIdx.x, lane = tid & 31, warp = tid >> 5;
    const int gid = lane >> 2, tig = lane & 3;
    const int cob = (warp >> 1) * 32, nb = (warp & 1) * 64;
    const int bh = blockIdx.x, t = blockIdx.y, cog = blockIdx.z;
    const int b = bh >> 7, h = bh & 127;
    const int kh0 = (h == 0) ? 1 : 0;
    const int kh1 = (h == 127) ? 1 : 2;
    const int nch = (kh1 - kh0 + 1) * 24;   // chunks: (kh)(ci8)(kw), kw fastest; 48 or 72 (even)
    const uint32_t smbase = smem_u32(sm);

    float acc[2][8][4];
    #pragma unroll
    for (int i = 0; i < 2; ++i)
        #pragma unroll
        for (int j = 0; j < 8; ++j)
            #pragma unroll
            for (int l = 0; l < 4; ++l) acc[i][j][l] = 0.f;

    auto fill = [&](int it) {
        const int kh = kh0 + it / 24;
        const int rem = it % 24;
        const int ci8 = rem / 3, kw = rem % 3;
        // A: [t][kh*3+kw][cog*128 + row][ci8*32 + ...]
        const __half* wp = g_w16 + (((size_t)t * 9 + kh * 3 + kw) * 256 + cog * 128) * 256
                         + ci8 * 32;
        const uint32_t dA = smbase + ((it % NSTG) * A_WORDS) * 4;
        #pragma unroll
        for (int i = 0; i < 2; ++i) {
            const int idx = tid + i * 256;
            const int row = idx >> 2, seg = idx & 3;
            cpa16(dA + (uint32_t)(row * CSA + seg * 4) * 4, wp + (size_t)row * 256 + seg * 8);
        }
        // B: halo rows w-1..128 — only when kw == 0
        if (kw == 0) {
            const int hsrc = h + kh - 1;
            const __half* xp = g_x16 + (((size_t)(b * H_ + hsrc)) << 7) * 256 + ci8 * 32;
            const uint32_t dB = smbase + (SBB + ((it / 3) % 3) * B_WORDS) * 4;
            #pragma unroll
            for (int i = 0; i < 3; ++i) {
                const int idx = tid + i * 256;
                if (idx < 520) {
                    const int row = idx >> 2, seg = idx & 3;
                    const int wsrc = row - 1;
                    const int sz = ((unsigned)wsrc < 128u) ? 16 : 0;
                    const int wc = min(max(wsrc, 0), 127);
                    cpa16z(dB + (uint32_t)(row * CSA + seg * 4) * 4,
                           xp + (size_t)wc * 256 + seg * 8, sz);
                }
            }
        }
    };

    auto compute = [&](int it) {
        const int kw = it % 3;
        const uint32_t* A  = sm + (it % NSTG) * A_WORDS;
        const uint32_t* Bp = sm + SBB + ((it / 3) % 3) * B_WORDS + kw * CSA;
        #pragma unroll
        for (int ks = 0; ks < 2; ++ks) {
            const int k0 = ks * 8;   // word offset (16 fp16)
            uint32_t af[2][4], bf[8][2];
            #pragma unroll
            for (int mi = 0; mi < 2; ++mi) {
                const int r = (cob + mi * 16 + gid) * CSA + k0 + tig;
                af[mi][0] = A[r];
                af[mi][1] = A[r + 8 * CSA];
                af[mi][2] = A[r + 4];
                af[mi][3] = A[r + 8 * CSA + 4];
            }
            #pragma unroll
            for (int ni = 0; ni < 8; ++ni) {
                const int r = (nb + ni * 8 + gid) * CSA + k0 + tig;
                bf[ni][0] = Bp[r];
                bf[ni][1] = Bp[r + 4];
            }
            #pragma unroll
            for (int mi = 0; mi < 2; ++mi)
                #pragma unroll
                for (int ni = 0; ni < 8; ++ni)
                    mma16(acc[mi][ni], af[mi], bf[ni]);
        }
    };

    // prologue: 4 fills in flight
    fill(0); CP_COMMIT();
    fill(1); CP_COMMIT();
    fill(2); CP_COMMIT();
    fill(3); CP_COMMIT();
    // paired mainloop: one wait + one barrier per 2 chunks
    for (int it = 0; it < nch; it += 2) {
        CP_WAIT2();              // fills <= it+1 complete (it+2, it+3 outstanding)
        __syncthreads();         // fences compute(it-2), compute(it-1) CTA-wide
        if (it + 4 < nch) fill(it + 4);
        CP_COMMIT();
        if (it + 5 < nch) fill(it + 5);
        CP_COMMIT();
        compute(it);
        compute(it + 1);
    }

    // epilogue: bias + store fp16
    __half* outp = (t == 0) ? g_q : (t == 1) ? g_k : g_v;
    const float* bias = (t == 0) ? bq : (t == 1) ? bk : bv;
    #pragma unroll
    for (int mi = 0; mi < 2; ++mi) {
        const int co0 = cog * 128 + cob + mi * 16 + gid;
        const float bv0 = bias[co0], bv1 = bias[co0 + 8];
        __half* r0 = outp + ((size_t)(b * C_ + co0) * HW) + h * 128;
        __half* r1 = r0 + (size_t)8 * HW;
        #pragma unroll
        for (int ni = 0; ni < 8; ++ni) {
            const int col = nb + ni * 8 + 2 * tig;
            *(__half2*)(r0 + col) = __floats2half2_rn(acc[mi][ni][0] + bv0, acc[mi][ni][1] + bv0);
            *(__half2*)(r1 + col) = __floats2half2_rn(acc[mi][ni][2] + bv1, acc[mi][ni][3] + bv1);
        }
    }
}

// ---------------- attention: fp16 tensor-core, 2 CTAs/SM --------------------
// Regions: Q (reused for P), K (reused for V^T), V. 3 regions -> 102 KB.
#define ASW 68                                  // words per row (128 fp16 + 8 pad)
#define AREG (128 * ASW)
#define ATTN_SMEM (3 * AREG * 4)                // 104448 B

__global__ __launch_bounds__(256, 2) void attn_kernel(float* __restrict__ out) {
    extern __shared__ uint32_t asm_[];
    uint32_t* qs  = asm_;
    uint32_t* ks  = qs + AREG;
    uint32_t* vs  = ks + AREG;
    uint32_t* vts = ks;                         // V^T overwrites K after S-GEMM

    const int bc = blockIdx.x;
    const size_t base = (size_t)bc * HW;
    const int tid = threadIdx.x;
    const int lane = tid & 31;
    const int warp = tid >> 5;
    const int gid = lane >> 2, tig = lane & 3;
    const uint32_t smbase = smem_u32(asm_);

    // group 0: Q + K
    #pragma unroll
    for (int i = 0; i < 8; ++i) {
        const int idx = tid + i * 256;
        const int r = idx >> 4, seg = idx & 15;
        const uint32_t doff = (uint32_t)(r * ASW + seg * 4) * 4;
        cpa16(smbase + doff,            g_q + base + (size_t)r * 128 + seg * 8);
        cpa16(smbase + AREG * 4 + doff, g_k + base + (size_t)r * 128 + seg * 8);
    }
    CP_COMMIT();
    // group 1: V (overlaps S + softmax)
    #pragma unroll
    for (int i = 0; i < 8; ++i) {
        const int idx = tid + i * 256;
        const int r = idx >> 4, seg = idx & 15;
        cpa16(smbase + 2 * AREG * 4 + (uint32_t)(r * ASW + seg * 4) * 4,
              g_v + base + (size_t)r * 128 + seg * 8);
    }
    CP_COMMIT();
    CP_WAIT1();
    __syncthreads();

    const uint32_t* qw = qs + warp * 16 * ASW;
    uint32_t* pw = qs + warp * 16 * ASW;

    // ---- S = Q K^T ----
    float sacc[16][4];
    #pragma unroll
    for (int nt = 0; nt < 16; ++nt)
        #pragma unroll
        for (int j = 0; j < 4; ++j) sacc[nt][j] = 0.f;

    #pragma unroll
    for (int kt = 0; kt < 8; ++kt) {
        const int k0 = kt * 8;
        uint32_t a[4];
        a[0] = qw[gid * ASW + k0 + tig];
        a[1] = qw[(gid + 8) * ASW + k0 + tig];
        a[2] = qw[gid * ASW + k0 + tig + 4];
        a[3] = qw[(gid + 8) * ASW + k0 + tig + 4];
        #pragma unroll
        for (int nt = 0; nt < 16; ++nt) {
            uint32_t b[2];
            b[0] = ks[(nt * 8 + gid) * ASW + k0 + tig];
            b[1] = ks[(nt * 8 + gid) * ASW + k0 + tig + 4];
            mma16(sacc[nt], a, b);
        }
    }

    // ---- softmax ----
    const float scale = rsqrtf(128.f);
    float m0 = -1e30f, m1 = -1e30f;
    #pragma unroll
    for (int nt = 0; nt < 16; ++nt) {
        #pragma unroll
        for (int j = 0; j < 4; ++j) sacc[nt][j] *= scale;
        m0 = fmaxf(m0, fmaxf(sacc[nt][0], sacc[nt][1]));
        m1 = fmaxf(m1, fmaxf(sacc[nt][2], sacc[nt][3]));
    }
    m0 = fmaxf(m0, __shfl_xor_sync(0xffffffffu, m0, 1));
    m0 = fmaxf(m0, __shfl_xor_sync(0xffffffffu, m0, 2));
    m1 = fmaxf(m1, __shfl_xor_sync(0xffffffffu, m1, 1));
    m1 = fmaxf(m1, __shfl_xor_sync(0xffffffffu, m1, 2));

    float e0 = 0.f, e1 = 0.f;
    #pragma unroll
    for (int nt = 0; nt < 16; ++nt) {
        sacc[nt][0] = __expf(sacc[nt][0] - m0);
        sacc[nt][1] = __expf(sacc[nt][1] - m0);
        sacc[nt][2] = __expf(sacc[nt][2] - m1);
        sacc[nt][3] = __expf(sacc[nt][3] - m1);
        e0 += sacc[nt][0] + sacc[nt][1];
        e1 += sacc[nt][2] + sacc[nt][3];
    }
    e0 += __shfl_xor_sync(0xffffffffu, e0, 1);
    e0 += __shfl_xor_sync(0xffffffffu, e0, 2);
    e1 += __shfl_xor_sync(0xffffffffu, e1, 1);
    e1 += __shfl_xor_sync(0xffffffffu, e1, 2);
    const float i0 = 1.f / e0, i1 = 1.f / e1;

    // store P (fp16 pairs) into warp's own Q region
    #pragma unroll
    for (int nt = 0; nt < 16; ++nt) {
        __half2 p0 = __floats2half2_rn(sacc[nt][0] * i0, sacc[nt][1] * i0);
        __half2 p1 = __floats2half2_rn(sacc[nt][2] * i1, sacc[nt][3] * i1);
        pw[gid * ASW + nt * 4 + tig]       = *(uint32_t*)&p0;
        pw[(gid + 8) * ASW + nt * 4 + tig] = *(uint32_t*)&p1;
    }
    __syncwarp();

    CP_WAIT0();
    __syncthreads();   // all warps done reading K; V landed

    // ---- transpose V: vs[g][w] -> vts[w][g] (vts overlays ks) ----
    {
        uint16_t* vth = (uint16_t*)vts;
        const int g = tid >> 1;
        const int wb = (tid & 1) * 64;
        #pragma unroll
        for (int w2 = 0; w2 < 32; ++w2) {
            const int w = wb + w2 * 2;
            const uint32_t pair = vs[g * ASW + (w >> 1)];
            vth[(size_t)w * (2 * ASW) + g]       = (uint16_t)(pair & 0xffff);
            vth[(size_t)(w + 1) * (2 * ASW) + g] = (uint16_t)(pair >> 16);
        }
    }
    __syncthreads();

    // ---- O = P V ----
    float oacc[16][4];
    #pragma unroll
    for (int nt = 0; nt < 16; ++nt)
        #pragma unroll
        for (int j = 0; j < 4; ++j) oacc[nt][j] = 0.f;

    #pragma unroll
    for (int kt = 0; kt < 8; ++kt) {
        const int k0 = kt * 8;
        uint32_t a[4];
        a[0] = pw[gid * ASW + k0 + tig];
        a[1] = pw[(gid + 8) * ASW + k0 + tig];
        a[2] = pw[gid * ASW + k0 + tig + 4];
        a[3] = pw[(gid + 8) * ASW + k0 + tig + 4];
        #pragma unroll
        for (int nt = 0; nt < 16; ++nt) {
            uint32_t b[2];
            b[0] = vts[(nt * 8 + gid) * ASW + k0 + tig];
            b[1] = vts[(nt * 8 + gid) * ASW + k0 + tig + 4];
            mma16(oacc[nt], a, b);
        }
    }

    float* op0 = out + base + (size_t)(warp * 16 + gid) * 128;
    float* op1 = op0 + 8 * 128;
    #pragma unroll
    for (int nt = 0; nt < 16; ++nt) {
        const int col = nt * 8 + 2 * tig;
        *(float2*)(op0 + col) = make_float2(oacc[nt][0], oacc[nt][1]);
        *(float2*)(op1 + col) = make_float2(oacc[nt][2], oacc[nt][3]);
    }
}

// ---------------------------------------------------------------------------
extern "C" void kernel_launch(void* const* d_in, const int* in_sizes, int n_in,
                              void* d_out, int out_size) {
    const float* x  = (const float*)d_in[0];
    const float* Wq = (const float*)d_in[1];
    const float* bq = (const float*)d_in[2];
    const float* Wk = (const float*)d_in[3];
    const float* bk = (const float*)d_in[4];
    const float* Wv = (const float*)d_in[5];
    const float* bv = (const float*)d_in[6];
    float* out = (float*)d_out;

    static bool attr_done = false;
    if (!attr_done) {
        cudaFuncSetAttribute(conv_kernel, cudaFuncAttributeMaxDynamicSharedMemorySize, CONV_SMEM);
        cudaFuncSetAttribute(attn_kernel, cudaFuncAttributeMaxDynamicSharedMemorySize, ATTN_SMEM);
        attr_done = true;
    }

    xcvt_kernel<<<dim3(512, 8, 16), dim3(32, 8)>>>(x);
    wcvt_kernel<<<dim3(256, 3), 256>>>(Wq, Wk, Wv);

    conv_kernel<<<dim3(B_ * H_, 3, 2), 256, CONV_SMEM>>>(bq, bk, bv);

    attn_kernel<<<B_ * C_, 256, ATTN_SMEM>>>(out);
}

// round 16
// speedup vs baseline: 1.1547x; 1.0919x over previous
#include <cuda_runtime.h>
#include <cuda_fp16.h>
#include <cstdint>
#include <math.h>

#define B_   16
#define C_   256
#define CIN  256
#define H_   128
#define W_   128
#define HW   (H_*W_)
#define TOT  ((size_t)B_*C_*HW)

// ---------------- device scratch (allocation-guard safe) -------------------
__device__ __half g_q[TOT];                       // fp16
__device__ __half g_k[TOT];
__device__ __half g_v[TOT];
__device__ __half g_x16[(size_t)B_*H_*W_*CIN];    // x transposed: [b][h][w][ci]
__device__ __half g_w16[(size_t)3*9*256*256];     // [t][kk][co][ci]

// ---------------- helpers ---------------------------------------------------
__device__ __forceinline__ uint32_t smem_u32(const void* p) {
    uint32_t a;
    asm("{ .reg .u64 t; cvta.to.shared.u64 t, %1; cvt.u32.u64 %0, t; }" : "=r"(a) : "l"(p));
    return a;
}
__device__ __forceinline__ void cpa16(uint32_t d, const void* s) {
    asm volatile("cp.async.cg.shared.global [%0], [%1], 16;" :: "r"(d), "l"(s));
}
__device__ __forceinline__ void cpa16z(uint32_t d, const void* s, int sz) {
    asm volatile("cp.async.cg.shared.global [%0], [%1], 16, %2;" :: "r"(d), "l"(s), "r"(sz));
}
#define CP_COMMIT() asm volatile("cp.async.commit_group;" ::: "memory")
#define CP_WAIT2()  asm volatile("cp.async.wait_group 2;" ::: "memory")
#define CP_WAIT1()  asm volatile("cp.async.wait_group 1;" ::: "memory")
#define CP_WAIT0()  asm volatile("cp.async.wait_group 0;" ::: "memory")

#define LDSM4(r0, r1, r2, r3, a)                                               \
    asm volatile("ldmatrix.sync.aligned.m8n8.x4.shared.b16 {%0,%1,%2,%3}, [%4];" \
        : "=r"(r0), "=r"(r1), "=r"(r2), "=r"(r3) : "r"(a))

__device__ __forceinline__ void mma16(float* c, const uint32_t* a, const uint32_t* b) {
    asm volatile(
        "mma.sync.aligned.m16n8k16.row.col.f32.f16.f16.f32 "
        "{%0,%1,%2,%3}, {%4,%5,%6,%7}, {%8,%9}, {%0,%1,%2,%3};"
        : "+f"(c[0]), "+f"(c[1]), "+f"(c[2]), "+f"(c[3])
        : "r"(a[0]), "r"(a[1]), "r"(a[2]), "r"(a[3]), "r"(b[0]), "r"(b[1]));
}

// ---------------- prologue 1: x NCHW f32 -> [b][h][w][ci] fp16 --------------
__global__ __launch_bounds__(256) void xcvt_kernel(const float* __restrict__ x) {
    __shared__ float t[32][33];
    const int bb = blockIdx.z;
    const int ci0 = blockIdx.y * 32, hw0 = blockIdx.x * 32;
    const int tx = threadIdx.x, ty = threadIdx.y;
    #pragma unroll
    for (int j = 0; j < 4; ++j)
        t[ty + 8 * j][tx] = x[(((size_t)bb * CIN + ci0 + ty + 8 * j) << 14) + hw0 + tx];
    __syncthreads();
    #pragma unroll
    for (int j = 0; j < 4; ++j)
        g_x16[(((size_t)bb << 14) + hw0 + ty + 8 * j) * CIN + ci0 + tx] =
            __float2half_rn(t[tx][ty + 8 * j]);
}

// ---------------- prologue 2: W [co][ci][3][3] -> [t][kk][co][ci] fp16 ------
__global__ __launch_bounds__(256) void wcvt_kernel(
    const float* __restrict__ Wq, const float* __restrict__ Wk, const float* __restrict__ Wv) {
    __shared__ float s[2304];
    const int co = blockIdx.x, t = blockIdx.y;
    const float* src = ((t == 0) ? Wq : (t == 1) ? Wk : Wv) + (size_t)co * 2304;
    for (int i = threadIdx.x; i < 2304; i += 256) s[i] = src[i];
    __syncthreads();
    const int ci = threadIdx.x;
    #pragma unroll
    for (int kk = 0; kk < 9; ++kk)
        g_w16[(((size_t)t * 9 + kk) * 256 + co) * 256 + ci] = __float2half_rn(s[ci * 9 + kk]);
}

// ---------------- conv: fp16 implicit GEMM, ldmatrix frags, 6-stage ring ----
// CTA: M=128 co x N=128 px, 256 thr / 8 warps, warp tile 32x64.
#define CSA      20                      // words per A row (32 fp16 + pad)
#define A_WORDS  (128 * CSA)             // 2560
#define B_WORDS  (130 * CSA)             // 2600
#define NSTG     6
#define SBB      (NSTG * A_WORDS)        // 15360
#define CONV_SMEM ((NSTG * A_WORDS + 3 * B_WORDS) * 4)   // 92640 B

__global__ __launch_bounds__(256, 2) void conv_kernel(
    const float* __restrict__ bq, const float* __restrict__ bk, const float* __restrict__ bv) {
    extern __shared__ uint32_t sm[];
    const int tid = threadIdx.x, lane = tid & 31, warp = tid >> 5;
    const int gid = lane >> 2, tig = lane & 3;
    const int cob = (warp >> 1) * 32, nb = (warp & 1) * 64;
    const int bh = blockIdx.x, t = blockIdx.y, cog = blockIdx.z;
    const int b = bh >> 7, h = bh & 127;
    const int kh0 = (h == 0) ? 1 : 0;
    const int kh1 = (h == 127) ? 1 : 2;
    const int nch = (kh1 - kh0 + 1) * 24;   // chunks: (kh)(ci8)(kw), kw fastest; even
    const uint32_t smbase = smem_u32(sm);

    // ldmatrix per-lane row offsets (words)
    const int rowA = (cob + (lane & 15)) * CSA + (lane >> 4) * 4;
    const int rowB = (nb + (lane & 7) + (lane >> 4) * 8) * CSA + ((lane >> 3) & 1) * 4;

    float acc[2][8][4];
    #pragma unroll
    for (int i = 0; i < 2; ++i)
        #pragma unroll
        for (int j = 0; j < 8; ++j)
            #pragma unroll
            for (int l = 0; l < 4; ++l) acc[i][j][l] = 0.f;

    auto fill = [&](int it) {
        const int kh = kh0 + it / 24;
        const int rem = it % 24;
        const int ci8 = rem / 3, kw = rem % 3;
        const __half* wp = g_w16 + (((size_t)t * 9 + kh * 3 + kw) * 256 + cog * 128) * 256
                         + ci8 * 32;
        const uint32_t dA = smbase + ((it % NSTG) * A_WORDS) * 4;
        #pragma unroll
        for (int i = 0; i < 2; ++i) {
            const int idx = tid + i * 256;
            const int row = idx >> 2, seg = idx & 3;
            cpa16(dA + (uint32_t)(row * CSA + seg * 4) * 4, wp + (size_t)row * 256 + seg * 8);
        }
        if (kw == 0) {
            const int hsrc = h + kh - 1;
            const __half* xp = g_x16 + (((size_t)(b * H_ + hsrc)) << 7) * 256 + ci8 * 32;
            const uint32_t dB = smbase + (SBB + ((it / 3) % 3) * B_WORDS) * 4;
            #pragma unroll
            for (int i = 0; i < 3; ++i) {
                const int idx = tid + i * 256;
                if (idx < 520) {
                    const int row = idx >> 2, seg = idx & 3;
                    const int wsrc = row - 1;
                    const int sz = ((unsigned)wsrc < 128u) ? 16 : 0;
                    const int wc = min(max(wsrc, 0), 127);
                    cpa16z(dB + (uint32_t)(row * CSA + seg * 4) * 4,
                           xp + (size_t)wc * 256 + seg * 8, sz);
                }
            }
        }
    };

    auto compute = [&](int it) {
        const uint32_t Ab = smbase + (uint32_t)((it % NSTG) * A_WORDS + rowA) * 4;
        const uint32_t Bb = smbase + (uint32_t)(SBB + ((it / 3) % 3) * B_WORDS
                                               + (it % 3) * CSA + rowB) * 4;
        #pragma unroll
        for (int ks = 0; ks < 2; ++ks) {
            const uint32_t k0b = (uint32_t)(ks * 8) * 4;   // 8 words per k-half
            uint32_t af[2][4], bf[8][2];
            LDSM4(af[0][0], af[0][1], af[0][2], af[0][3], Ab + k0b);
            LDSM4(af[1][0], af[1][1], af[1][2], af[1][3], Ab + (uint32_t)(16 * CSA) * 4 + k0b);
            #pragma unroll
            for (int ni2 = 0; ni2 < 8; ni2 += 2)
                LDSM4(bf[ni2][0], bf[ni2][1], bf[ni2 + 1][0], bf[ni2 + 1][1],
                      Bb + (uint32_t)(ni2 * 8 * CSA) * 4 + k0b);
            #pragma unroll
            for (int mi = 0; mi < 2; ++mi)
                #pragma unroll
                for (int ni = 0; ni < 8; ++ni)
                    mma16(acc[mi][ni], af[mi], bf[ni]);
        }
    };

    // prologue: 4 fills in flight
    fill(0); CP_COMMIT();
    fill(1); CP_COMMIT();
    fill(2); CP_COMMIT();
    fill(3); CP_COMMIT();
    // paired mainloop: one wait + one barrier per 2 chunks
    for (int it = 0; it < nch; it += 2) {
        CP_WAIT2();
        __syncthreads();
        if (it + 4 < nch) fill(it + 4);
        CP_COMMIT();
        if (it + 5 < nch) fill(it + 5);
        CP_COMMIT();
        compute(it);
        compute(it + 1);
    }

    // epilogue: bias + store fp16
    __half* outp = (t == 0) ? g_q : (t == 1) ? g_k : g_v;
    const float* bias = (t == 0) ? bq : (t == 1) ? bk : bv;
    #pragma unroll
    for (int mi = 0; mi < 2; ++mi) {
        const int co0 = cog * 128 + cob + mi * 16 + gid;
        const float bv0 = bias[co0], bv1 = bias[co0 + 8];
        __half* r0 = outp + ((size_t)(b * C_ + co0) * HW) + h * 128;
        __half* r1 = r0 + (size_t)8 * HW;
        #pragma unroll
        for (int ni = 0; ni < 8; ++ni) {
            const int col = nb + ni * 8 + 2 * tig;
            *(__half2*)(r0 + col) = __floats2half2_rn(acc[mi][ni][0] + bv0, acc[mi][ni][1] + bv0);
            *(__half2*)(r1 + col) = __floats2half2_rn(acc[mi][ni][2] + bv1, acc[mi][ni][3] + bv1);
        }
    }
}

// ---------------- attention: fp16 tensor-core, 2 CTAs/SM --------------------
#define ASW 68                                  // words per row (128 fp16 + 8 pad)
#define AREG (128 * ASW)
#define ATTN_SMEM (3 * AREG * 4)                // 104448 B

__global__ __launch_bounds__(256, 2) void attn_kernel(float* __restrict__ out) {
    extern __shared__ uint32_t asm_[];
    uint32_t* qs  = asm_;
    uint32_t* ks  = qs + AREG;
    uint32_t* vs  = ks + AREG;
    uint32_t* vts = ks;                         // V^T overwrites K after S-GEMM

    const int bc = blockIdx.x;
    const size_t base = (size_t)bc * HW;
    const int tid = threadIdx.x;
    const int lane = tid & 31;
    const int warp = tid >> 5;
    const int gid = lane >> 2, tig = lane & 3;
    const uint32_t smbase = smem_u32(asm_);

    // group 0: Q + K
    #pragma unroll
    for (int i = 0; i < 8; ++i) {
        const int idx = tid + i * 256;
        const int r = idx >> 4, seg = idx & 15;
        const uint32_t doff = (uint32_t)(r * ASW + seg * 4) * 4;
        cpa16(smbase + doff,            g_q + base + (size_t)r * 128 + seg * 8);
        cpa16(smbase + AREG * 4 + doff, g_k + base + (size_t)r * 128 + seg * 8);
    }
    CP_COMMIT();
    // group 1: V (overlaps S + softmax)
    #pragma unroll
    for (int i = 0; i < 8; ++i) {
        const int idx = tid + i * 256;
        const int r = idx >> 4, seg = idx & 15;
        cpa16(smbase + 2 * AREG * 4 + (uint32_t)(r * ASW + seg * 4) * 4,
              g_v + base + (size_t)r * 128 + seg * 8);
    }
    CP_COMMIT();
    CP_WAIT1();
    __syncthreads();

    const uint32_t* qw = qs + warp * 16 * ASW;
    uint32_t* pw = qs + warp * 16 * ASW;

    // ---- S = Q K^T ----
    float sacc[16][4];
    #pragma unroll
    for (int nt = 0; nt < 16; ++nt)
        #pragma unroll
        for (int j = 0; j < 4; ++j) sacc[nt][j] = 0.f;

    #pragma unroll
    for (int kt = 0; kt < 8; ++kt) {
        const int k0 = kt * 8;
        uint32_t a[4];
        a[0] = qw[gid * ASW + k0 + tig];
        a[1] = qw[(gid + 8) * ASW + k0 + tig];
        a[2] = qw[gid * ASW + k0 + tig + 4];
        a[3] = qw[(gid + 8) * ASW + k0 + tig + 4];
        #pragma unroll
        for (int nt = 0; nt < 16; ++nt) {
            uint32_t b[2];
            b[0] = ks[(nt * 8 + gid) * ASW + k0 + tig];
            b[1] = ks[(nt * 8 + gid) * ASW + k0 + tig + 4];
            mma16(sacc[nt], a, b);
        }
    }

    // ---- softmax ----
    const float scale = rsqrtf(128.f);
    float m0 = -1e30f, m1 = -1e30f;
    #pragma unroll
    for (int nt = 0; nt < 16; ++nt) {
        #pragma unroll
        for (int j = 0; j < 4; ++j) sacc[nt][j] *= scale;
        m0 = fmaxf(m0, fmaxf(sacc[nt][0], sacc[nt][1]));
        m1 = fmaxf(m1, fmaxf(sacc[nt][2], sacc[nt][3]));
    }
    m0 = fmaxf(m0, __shfl_xor_sync(0xffffffffu, m0, 1));
    m0 = fmaxf(m0, __shfl_xor_sync(0xffffffffu, m0, 2));
    m1 = fmaxf(m1, __shfl_xor_sync(0xffffffffu, m1, 1));
    m1 = fmaxf(m1, __shfl_xor_sync(0xffffffffu, m1, 2));

    float e0 = 0.f, e1 = 0.f;
    #pragma unroll
    for (int nt = 0; nt < 16; ++nt) {
        sacc[nt][0] = __expf(sacc[nt][0] - m0);
        sacc[nt][1] = __expf(sacc[nt][1] - m0);
        sacc[nt][2] = __expf(sacc[nt][2] - m1);
        sacc[nt][3] = __expf(sacc[nt][3] - m1);
        e0 += sacc[nt][0] + sacc[nt][1];
        e1 += sacc[nt][2] + sacc[nt][3];
    }
    e0 += __shfl_xor_sync(0xffffffffu, e0, 1);
    e0 += __shfl_xor_sync(0xffffffffu, e0, 2);
    e1 += __shfl_xor_sync(0xffffffffu, e1, 1);
    e1 += __shfl_xor_sync(0xffffffffu, e1, 2);
    const float i0 = 1.f / e0, i1 = 1.f / e1;

    // store P (fp16 pairs) into warp's own Q region
    #pragma unroll
    for (int nt = 0; nt < 16; ++nt) {
        __half2 p0 = __floats2half2_rn(sacc[nt][0] * i0, sacc[nt][1] * i0);
        __half2 p1 = __floats2half2_rn(sacc[nt][2] * i1, sacc[nt][3] * i1);
        pw[gid * ASW + nt * 4 + tig]       = *(uint32_t*)&p0;
        pw[(gid + 8) * ASW + nt * 4 + tig] = *(uint32_t*)&p1;
    }
    __syncwarp();

    CP_WAIT0();
    __syncthreads();   // all warps done reading K; V landed

    // ---- transpose V: vs[g][w] -> vts[w][g] (vts overlays ks) ----
    {
        uint16_t* vth = (uint16_t*)vts;
        const int g = tid >> 1;
        const int wb = (tid & 1) * 64;
        #pragma unroll
        for (int w2 = 0; w2 < 32; ++w2) {
            const int w = wb + w2 * 2;
            const uint32_t pair = vs[g * ASW + (w >> 1)];
            vth[(size_t)w * (2 * ASW) + g]       = (uint16_t)(pair & 0xffff);
            vth[(size_t)(w + 1) * (2 * ASW) + g] = (uint16_t)(pair >> 16);
        }
    }
    __syncthreads();

    // ---- O = P V ----
    float oacc[16][4];
    #pragma unroll
    for (int nt = 0; nt < 16; ++nt)
        #pragma unroll
        for (int j = 0; j < 4; ++j) oacc[nt][j] = 0.f;

    #pragma unroll
    for (int kt = 0; kt < 8; ++kt) {
        const int k0 = kt * 8;
        uint32_t a[4];
        a[0] = pw[gid * ASW + k0 + tig];
        a[1] = pw[(gid + 8) * ASW + k0 + tig];
        a[2] = pw[gid * ASW + k0 + tig + 4];
        a[3] = pw[(gid + 8) * ASW + k0 + tig + 4];
        #pragma unroll
        for (int nt = 0; nt < 16; ++nt) {
            uint32_t b[2];
            b[0] = vts[(nt * 8 + gid) * ASW + k0 + tig];
            b[1] = vts[(nt * 8 + gid) * ASW + k0 + tig + 4];
            mma16(oacc[nt], a, b);
        }
    }

    float* op0 = out + base + (size_t)(warp * 16 + gid) * 128;
    float* op1 = op0 + 8 * 128;
    #pragma unroll
    for (int nt = 0; nt < 16; ++nt) {
        const int col = nt * 8 + 2 * tig;
        *(float2*)(op0 + col) = make_float2(oacc[nt][0], oacc[nt][1]);
        *(float2*)(op1 + col) = make_float2(oacc[nt][2], oacc[nt][3]);
    }
}

// ---------------------------------------------------------------------------
extern "C" void kernel_launch(void* const* d_in, const int* in_sizes, int n_in,
                              void* d_out, int out_size) {
    const float* x  = (const float*)d_in[0];
    const float* Wq = (const float*)d_in[1];
    const float* bq = (const float*)d_in[2];
    const float* Wk = (const float*)d_in[3];
    const float* bk = (const float*)d_in[4];
    const float* Wv = (const float*)d_in[5];
    const float* bv = (const float*)d_in[6];
    float* out = (float*)d_out;

    static bool attr_done = false;
    if (!attr_done) {
        cudaFuncSetAttribute(conv_kernel, cudaFuncAttributeMaxDynamicSharedMemorySize, CONV_SMEM);
        cudaFuncSetAttribute(attn_kernel, cudaFuncAttributeMaxDynamicSharedMemorySize, ATTN_SMEM);
        attr_done = true;
    }

    xcvt_kernel<<<dim3(512, 8, 16), dim3(32, 8)>>>(x);
    wcvt_kernel<<<dim3(256, 3), 256>>>(Wq, Wk, Wv);

    conv_kernel<<<dim3(B_ * H_, 3, 2), 256, CONV_SMEM>>>(bq, bk, bv);

    attn_kernel<<<B_ * C_, 256, ATTN_SMEM>>>(out);
}

// round 17
// speedup vs baseline: 1.1842x; 1.0256x over previous
#include <cuda_runtime.h>
#include <cuda_fp16.h>
#include <cstdint>
#include <math.h>

#define B_   16
#define C_   256
#define CIN  256
#define H_   128
#define W_   128
#define HW   (H_*W_)
#define TOT  ((size_t)B_*C_*HW)

// ---------------- device scratch (allocation-guard safe) -------------------
__device__ __half g_q[TOT];                       // fp16 (pre-scaled by 1/sqrt(128))
__device__ __half g_k[TOT];
__device__ __half g_v[TOT];
__device__ __half g_x16[(size_t)B_*H_*W_*CIN];    // x transposed: [b][h][w][ci]
__device__ __half g_w16[(size_t)3*9*256*256];     // [t][kk][co][ci]

// ---------------- helpers ---------------------------------------------------
__device__ __forceinline__ uint32_t smem_u32(const void* p) {
    uint32_t a;
    asm("{ .reg .u64 t; cvta.to.shared.u64 t, %1; cvt.u32.u64 %0, t; }" : "=r"(a) : "l"(p));
    return a;
}
__device__ __forceinline__ void cpa16(uint32_t d, const void* s) {
    asm volatile("cp.async.cg.shared.global [%0], [%1], 16;" :: "r"(d), "l"(s));
}
__device__ __forceinline__ void cpa16z(uint32_t d, const void* s, int sz) {
    asm volatile("cp.async.cg.shared.global [%0], [%1], 16, %2;" :: "r"(d), "l"(s), "r"(sz));
}
#define CP_COMMIT() asm volatile("cp.async.commit_group;" ::: "memory")
#define CP_WAIT2()  asm volatile("cp.async.wait_group 2;" ::: "memory")
#define CP_WAIT1()  asm volatile("cp.async.wait_group 1;" ::: "memory")
#define CP_WAIT0()  asm volatile("cp.async.wait_group 0;" ::: "memory")

#define LDSM4(r0, r1, r2, r3, a)                                               \
    asm volatile("ldmatrix.sync.aligned.m8n8.x4.shared.b16 {%0,%1,%2,%3}, [%4];" \
        : "=r"(r0), "=r"(r1), "=r"(r2), "=r"(r3) : "r"(a))
#define LDSM4T(r0, r1, r2, r3, a)                                              \
    asm volatile("ldmatrix.sync.aligned.m8n8.x4.trans.shared.b16 {%0,%1,%2,%3}, [%4];" \
        : "=r"(r0), "=r"(r1), "=r"(r2), "=r"(r3) : "r"(a))

__device__ __forceinline__ void mma16(float* c, const uint32_t* a, const uint32_t* b) {
    asm volatile(
        "mma.sync.aligned.m16n8k16.row.col.f32.f16.f16.f32 "
        "{%0,%1,%2,%3}, {%4,%5,%6,%7}, {%8,%9}, {%0,%1,%2,%3};"
        : "+f"(c[0]), "+f"(c[1]), "+f"(c[2]), "+f"(c[3])
        : "r"(a[0]), "r"(a[1]), "r"(a[2]), "r"(a[3]), "r"(b[0]), "r"(b[1]));
}

// ---------------- prologue 1: x NCHW f32 -> [b][h][w][ci] fp16 --------------
__global__ __launch_bounds__(256) void xcvt_kernel(const float* __restrict__ x) {
    __shared__ float t[32][33];
    const int bb = blockIdx.z;
    const int ci0 = blockIdx.y * 32, hw0 = blockIdx.x * 32;
    const int tx = threadIdx.x, ty = threadIdx.y;
    #pragma unroll
    for (int j = 0; j < 4; ++j)
        t[ty + 8 * j][tx] = x[(((size_t)bb * CIN + ci0 + ty + 8 * j) << 14) + hw0 + tx];
    __syncthreads();
    #pragma unroll
    for (int j = 0; j < 4; ++j)
        g_x16[(((size_t)bb << 14) + hw0 + ty + 8 * j) * CIN + ci0 + tx] =
            __float2half_rn(t[tx][ty + 8 * j]);
}

// ---------------- prologue 2: W [co][ci][3][3] -> [t][kk][co][ci] fp16 ------
__global__ __launch_bounds__(256) void wcvt_kernel(
    const float* __restrict__ Wq, const float* __restrict__ Wk, const float* __restrict__ Wv) {
    __shared__ float s[2304];
    const int co = blockIdx.x, t = blockIdx.y;
    const float* src = ((t == 0) ? Wq : (t == 1) ? Wk : Wv) + (size_t)co * 2304;
    for (int i = threadIdx.x; i < 2304; i += 256) s[i] = src[i];
    __syncthreads();
    const int ci = threadIdx.x;
    #pragma unroll
    for (int kk = 0; kk < 9; ++kk)
        g_w16[(((size_t)t * 9 + kk) * 256 + co) * 256 + ci] = __float2half_rn(s[ci * 9 + kk]);
}

// ---------------- conv: fp16 implicit GEMM, ldmatrix frags, 6-stage ring ----
#define CSA      20                      // words per A row (32 fp16 + pad)
#define A_WORDS  (128 * CSA)             // 2560
#define B_WORDS  (130 * CSA)             // 2600
#define NSTG     6
#define SBB      (NSTG * A_WORDS)        // 15360
#define CONV_SMEM ((NSTG * A_WORDS + 3 * B_WORDS) * 4)   // 92640 B

__global__ __launch_bounds__(256, 2) void conv_kernel(
    const float* __restrict__ bq, const float* __restrict__ bk, const float* __restrict__ bv) {
    extern __shared__ uint32_t sm[];
    const int tid = threadIdx.x, lane = tid & 31, warp = tid >> 5;
    const int gid = lane >> 2, tig = lane & 3;
    const int cob = (warp >> 1) * 32, nb = (warp & 1) * 64;
    const int bh = blockIdx.x, t = blockIdx.y, cog = blockIdx.z;
    const int b = bh >> 7, h = bh & 127;
    const int kh0 = (h == 0) ? 1 : 0;
    const int kh1 = (h == 127) ? 1 : 2;
    const int nch = (kh1 - kh0 + 1) * 24;
    const uint32_t smbase = smem_u32(sm);

    const int rowA = (cob + (lane & 15)) * CSA + (lane >> 4) * 4;
    const int rowB = (nb + (lane & 7) + (lane >> 4) * 8) * CSA + ((lane >> 3) & 1) * 4;

    float acc[2][8][4];
    #pragma unroll
    for (int i = 0; i < 2; ++i)
        #pragma unroll
        for (int j = 0; j < 8; ++j)
            #pragma unroll
            for (int l = 0; l < 4; ++l) acc[i][j][l] = 0.f;

    auto fill = [&](int it) {
        const int kh = kh0 + it / 24;
        const int rem = it % 24;
        const int ci8 = rem / 3, kw = rem % 3;
        const __half* wp = g_w16 + (((size_t)t * 9 + kh * 3 + kw) * 256 + cog * 128) * 256
                         + ci8 * 32;
        const uint32_t dA = smbase + ((it % NSTG) * A_WORDS) * 4;
        #pragma unroll
        for (int i = 0; i < 2; ++i) {
            const int idx = tid + i * 256;
            const int row = idx >> 2, seg = idx & 3;
            cpa16(dA + (uint32_t)(row * CSA + seg * 4) * 4, wp + (size_t)row * 256 + seg * 8);
        }
        if (kw == 0) {
            const int hsrc = h + kh - 1;
            const __half* xp = g_x16 + (((size_t)(b * H_ + hsrc)) << 7) * 256 + ci8 * 32;
            const uint32_t dB = smbase + (SBB + ((it / 3) % 3) * B_WORDS) * 4;
            #pragma unroll
            for (int i = 0; i < 3; ++i) {
                const int idx = tid + i * 256;
                if (idx < 520) {
                    const int row = idx >> 2, seg = idx & 3;
                    const int wsrc = row - 1;
                    const int sz = ((unsigned)wsrc < 128u) ? 16 : 0;
                    const int wc = min(max(wsrc, 0), 127);
                    cpa16z(dB + (uint32_t)(row * CSA + seg * 4) * 4,
                           xp + (size_t)wc * 256 + seg * 8, sz);
                }
            }
        }
    };

    auto compute = [&](int it) {
        const uint32_t Ab = smbase + (uint32_t)((it % NSTG) * A_WORDS + rowA) * 4;
        const uint32_t Bb = smbase + (uint32_t)(SBB + ((it / 3) % 3) * B_WORDS
                                               + (it % 3) * CSA + rowB) * 4;
        #pragma unroll
        for (int ks = 0; ks < 2; ++ks) {
            const uint32_t k0b = (uint32_t)(ks * 8) * 4;
            uint32_t af[2][4], bf[8][2];
            LDSM4(af[0][0], af[0][1], af[0][2], af[0][3], Ab + k0b);
            LDSM4(af[1][0], af[1][1], af[1][2], af[1][3], Ab + (uint32_t)(16 * CSA) * 4 + k0b);
            #pragma unroll
            for (int ni2 = 0; ni2 < 8; ni2 += 2)
                LDSM4(bf[ni2][0], bf[ni2][1], bf[ni2 + 1][0], bf[ni2 + 1][1],
                      Bb + (uint32_t)(ni2 * 8 * CSA) * 4 + k0b);
            #pragma unroll
            for (int mi = 0; mi < 2; ++mi)
                #pragma unroll
                for (int ni = 0; ni < 8; ++ni)
                    mma16(acc[mi][ni], af[mi], bf[ni]);
        }
    };

    fill(0); CP_COMMIT();
    fill(1); CP_COMMIT();
    fill(2); CP_COMMIT();
    fill(3); CP_COMMIT();
    for (int it = 0; it < nch; it += 2) {
        CP_WAIT2();
        __syncthreads();
        if (it + 4 < nch) fill(it + 4);
        CP_COMMIT();
        if (it + 5 < nch) fill(it + 5);
        CP_COMMIT();
        compute(it);
        compute(it + 1);
    }

    // epilogue: bias (+ q pre-scale) + store fp16
    __half* outp = (t == 0) ? g_q : (t == 1) ? g_k : g_v;
    const float* bias = (t == 0) ? bq : (t == 1) ? bk : bv;
    const float osc = (t == 0) ? rsqrtf(128.f) : 1.f;
    #pragma unroll
    for (int mi = 0; mi < 2; ++mi) {
        const int co0 = cog * 128 + cob + mi * 16 + gid;
        const float bv0 = bias[co0], bv1 = bias[co0 + 8];
        __half* r0 = outp + ((size_t)(b * C_ + co0) * HW) + h * 128;
        __half* r1 = r0 + (size_t)8 * HW;
        #pragma unroll
        for (int ni = 0; ni < 8; ++ni) {
            const int col = nb + ni * 8 + 2 * tig;
            *(__half2*)(r0 + col) = __floats2half2_rn((acc[mi][ni][0] + bv0) * osc,
                                                      (acc[mi][ni][1] + bv0) * osc);
            *(__half2*)(r1 + col) = __floats2half2_rn((acc[mi][ni][2] + bv1) * osc,
                                                      (acc[mi][ni][3] + bv1) * osc);
        }
    }
}

// ---------------- attention: fp16 tensor-core, ldmatrix, 2 CTAs/SM ----------
// Regions: Q (reused for P), K, V. PV uses ldmatrix.trans on V directly.
#define ASW 68                                  // words per row (128 fp16 + 8 pad)
#define AREG (128 * ASW)
#define ATTN_SMEM (3 * AREG * 4)                // 104448 B

__global__ __launch_bounds__(256, 2) void attn_kernel(float* __restrict__ out) {
    extern __shared__ uint32_t asm_[];
    const int bc = blockIdx.x;
    const size_t base = (size_t)bc * HW;
    const int tid = threadIdx.x;
    const int lane = tid & 31;
    const int warp = tid >> 5;
    const int gid = lane >> 2, tig = lane & 3;
    const uint32_t smbase = smem_u32(asm_);

    // group 0: Q + K
    #pragma unroll
    for (int i = 0; i < 8; ++i) {
        const int idx = tid + i * 256;
        const int r = idx >> 4, seg = idx & 15;
        const uint32_t doff = (uint32_t)(r * ASW + seg * 4) * 4;
        cpa16(smbase + doff,            g_q + base + (size_t)r * 128 + seg * 8);
        cpa16(smbase + AREG * 4 + doff, g_k + base + (size_t)r * 128 + seg * 8);
    }
    CP_COMMIT();
    // group 1: V (overlaps S + softmax)
    #pragma unroll
    for (int i = 0; i < 8; ++i) {
        const int idx = tid + i * 256;
        const int r = idx >> 4, seg = idx & 15;
        cpa16(smbase + 2 * AREG * 4 + (uint32_t)(r * ASW + seg * 4) * 4,
              g_v + base + (size_t)r * 128 + seg * 8);
    }
    CP_COMMIT();
    CP_WAIT1();
    __syncthreads();

    // ldmatrix lane bases
    const uint32_t qbase = smbase
        + (uint32_t)((warp * 16 + (lane & 15)) * ASW + (lane >> 4) * 4) * 4;       // A (Q / P)
    const uint32_t kbase = smbase + AREG * 4
        + (uint32_t)(((lane & 7) + (lane >> 4) * 8) * ASW + ((lane >> 3) & 1) * 4) * 4;  // B (K)
    const uint32_t vbase = smbase + 2 * AREG * 4
        + (uint32_t)(((lane & 7) + ((lane >> 3) & 1) * 8) * ASW + (lane >> 4) * 4) * 4;  // B^T (V)

    uint32_t* pw = asm_ + warp * 16 * ASW;      // P overwrites warp's Q rows

    // ---- S = Q K^T ----
    float sacc[16][4];
    #pragma unroll
    for (int nt = 0; nt < 16; ++nt)
        #pragma unroll
        for (int j = 0; j < 4; ++j) sacc[nt][j] = 0.f;

    #pragma unroll
    for (int kt = 0; kt < 8; ++kt) {
        const uint32_t k0b = (uint32_t)kt * 32;     // 8 words
        uint32_t a[4];
        LDSM4(a[0], a[1], a[2], a[3], qbase + k0b);
        #pragma unroll
        for (int nt2 = 0; nt2 < 16; nt2 += 2) {
            uint32_t b0, b1, b2, b3;
            LDSM4(b0, b1, b2, b3, kbase + (uint32_t)(nt2 * 8 * ASW) * 4 + k0b);
            uint32_t bb0[2] = { b0, b1 }, bb1[2] = { b2, b3 };
            mma16(sacc[nt2],     a, bb0);
            mma16(sacc[nt2 + 1], a, bb1);
        }
    }

    // ---- softmax (q pre-scaled in conv; no scale here) ----
    float m0 = -1e30f, m1 = -1e30f;
    #pragma unroll
    for (int nt = 0; nt < 16; ++nt) {
        m0 = fmaxf(m0, fmaxf(sacc[nt][0], sacc[nt][1]));
        m1 = fmaxf(m1, fmaxf(sacc[nt][2], sacc[nt][3]));
    }
    m0 = fmaxf(m0, __shfl_xor_sync(0xffffffffu, m0, 1));
    m0 = fmaxf(m0, __shfl_xor_sync(0xffffffffu, m0, 2));
    m1 = fmaxf(m1, __shfl_xor_sync(0xffffffffu, m1, 1));
    m1 = fmaxf(m1, __shfl_xor_sync(0xffffffffu, m1, 2));

    float e0 = 0.f, e1 = 0.f;
    #pragma unroll
    for (int nt = 0; nt < 16; ++nt) {
        sacc[nt][0] = __expf(sacc[nt][0] - m0);
        sacc[nt][1] = __expf(sacc[nt][1] - m0);
        sacc[nt][2] = __expf(sacc[nt][2] - m1);
        sacc[nt][3] = __expf(sacc[nt][3] - m1);
        e0 += sacc[nt][0] + sacc[nt][1];
        e1 += sacc[nt][2] + sacc[nt][3];
    }
    e0 += __shfl_xor_sync(0xffffffffu, e0, 1);
    e0 += __shfl_xor_sync(0xffffffffu, e0, 2);
    e1 += __shfl_xor_sync(0xffffffffu, e1, 1);
    e1 += __shfl_xor_sync(0xffffffffu, e1, 2);
    const float i0 = 1.f / e0, i1 = 1.f / e1;

    // store P (fp16 pairs) into warp's own Q region
    #pragma unroll
    for (int nt = 0; nt < 16; ++nt) {
        __half2 p0 = __floats2half2_rn(sacc[nt][0] * i0, sacc[nt][1] * i0);
        __half2 p1 = __floats2half2_rn(sacc[nt][2] * i1, sacc[nt][3] * i1);
        pw[gid * ASW + nt * 4 + tig]       = *(uint32_t*)&p0;
        pw[(gid + 8) * ASW + nt * 4 + tig] = *(uint32_t*)&p1;
    }
    __syncwarp();

    CP_WAIT0();      // V landed (this thread's copies); no cross-warp smem dep for PV
    __syncthreads(); // make all V copies + P stores visible CTA-wide

    // ---- O = P V (V via ldmatrix.trans; no manual transpose) ----
    float oacc[16][4];
    #pragma unroll
    for (int nt = 0; nt < 16; ++nt)
        #pragma unroll
        for (int j = 0; j < 4; ++j) oacc[nt][j] = 0.f;

    #pragma unroll
    for (int kt = 0; kt < 8; ++kt) {
        const uint32_t k0b = (uint32_t)kt * 32;
        uint32_t a[4];
        LDSM4(a[0], a[1], a[2], a[3], qbase + k0b);   // P from warp's Q region
        #pragma unroll
        for (int nt2 = 0; nt2 < 16; nt2 += 2) {
            uint32_t b0, b1, b2, b3;
            LDSM4T(b0, b1, b2, b3,
                   vbase + (uint32_t)(kt * 16 * ASW) * 4 + (uint32_t)nt2 * 16);
            uint32_t bb0[2] = { b0, b1 }, bb1[2] = { b2, b3 };
            mma16(oacc[nt2],     a, bb0);
            mma16(oacc[nt2 + 1], a, bb1);
        }
    }

    float* op0 = out + base + (size_t)(warp * 16 + gid) * 128;
    float* op1 = op0 + 8 * 128;
    #pragma unroll
    for (int nt = 0; nt < 16; ++nt) {
        const int col = nt * 8 + 2 * tig;
        *(float2*)(op0 + col) = make_float2(oacc[nt][0], oacc[nt][1]);
        *(float2*)(op1 + col) = make_float2(oacc[nt][2], oacc[nt][3]);
    }
}

// ---------------------------------------------------------------------------
extern "C" void kernel_launch(void* const* d_in, const int* in_sizes, int n_in,
                              void* d_out, int out_size) {
    const float* x  = (const float*)d_in[0];
    const float* Wq = (const float*)d_in[1];
    const float* bq = (const float*)d_in[2];
    const float* Wk = (const float*)d_in[3];
    const float* bk = (const float*)d_in[4];
    const float* Wv = (const float*)d_in[5];
    const float* bv = (const float*)d_in[6];
    float* out = (float*)d_out;

    static bool attr_done = false;
    if (!attr_done) {
        cudaFuncSetAttribute(conv_kernel, cudaFuncAttributeMaxDynamicSharedMemorySize, CONV_SMEM);
        cudaFuncSetAttribute(attn_kernel, cudaFuncAttributeMaxDynamicSharedMemorySize, ATTN_SMEM);
        attr_done = true;
    }

    xcvt_kernel<<<dim3(512, 8, 16), dim3(32, 8)>>>(x);
    wcvt_kernel<<<dim3(256, 3), 256>>>(Wq, Wk, Wv);

    conv_kernel<<<dim3(B_ * H_, 3, 2), 256, CONV_SMEM>>>(bq, bk, bv);

    attn_kernel<<<B_ * C_, 256, ATTN_SMEM>>>(out);
}